// round 12
// baseline (speedup 1.0000x reference)
#include <cuda_runtime.h>
#include <math.h>

// Problem constants: z_e [32,64,32,32] f32, emb [1024,64] f32
// Output (f32): z_st [2097152] | loss | perplexity | encodings [32768,1024]
#define NPTS   32768
#define DDIM   64
#define KCODES 1024
#define HWSZ   1024
#define OFF_LOSS 2097152
#define OFF_PERP 2097153
#define OFF_ENC  2097154     // byte offset 8 mod 16 -> encodings only 8B-aligned
#define TK 128               // codes per CTA (one split)
#define NSPLIT 8             // code-axis splits per point
#define NGRP   128           // point groups of 256

__device__ float g_pd[NSPLIT * NPTS];   // partial best dist per (split, point)
__device__ int   g_pk[NSPLIT * NPTS];   // partial best code  per (split, point)
__device__ int   g_hist[KCODES];
__device__ float g_losspart[256];

// ---- packed f32x2: two independent IEEE-rn fp32 FMAs (bit-identical to 2x fmaf)
__device__ __forceinline__ unsigned long long fma2(unsigned long long a,
                                                   unsigned long long b,
                                                   unsigned long long c) {
    unsigned long long d;
    asm("fma.rn.f32x2 %0, %1, %2, %3;" : "=l"(d) : "l"(a), "l"(b), "l"(c));
    return d;
}
__device__ __forceinline__ unsigned long long splat2(float v) {
    unsigned long long r;
    asm("mov.b64 %0, {%1, %1};" : "=l"(r) : "f"(v));
    return r;
}
__device__ __forceinline__ void unpack2(unsigned long long p, float& lo, float& hi) {
    asm("mov.b64 {%0, %1}, %2;" : "=f"(lo), "=f"(hi) : "l"(p));
}

// Kernel 1: distance partials. Grid = 1024 CTAs x 256 threads.
// CTA (g, s): points g*256..g*256+255 (1 per thread) x codes s*128..s*128+127.
// 1 point/thread keeps regs ~120 -> 2 CTAs of 256 = 16 warps/SM (vs 8 at
// 2pt/254regs): doubles latency hiding so the FFMA2 pipe floor binds.
__global__ void __launch_bounds__(256, 2) vq_main(const float* __restrict__ z_e,
                                                  const float* __restrict__ emb,
                                                  float* __restrict__ out) {
    __shared__ float sEt[DDIM][TK];   // d-major transposed tile
    __shared__ float sN[TK];

    const int tid = threadIdx.x;
    const int bid = blockIdx.x;
    const int s   = bid & (NSPLIT - 1);
    const int g   = bid >> 3;
    const int kt0 = s * TK;

    // Zero 1/1024 of the encodings region (coalesced STG.64.CS; region is
    // only 8B-aligned so float2 is max width). Stream-ordered before merge.
    {
        float2* encB = (float2*)(out + (size_t)OFF_ENC) + (size_t)bid * 16384;
        const float2 z2 = make_float2(0.f, 0.f);
        #pragma unroll 8
        for (int i = 0; i < 64; i++)
            __stcs(&encB[tid + i * 256], z2);
    }
    // Zero the histogram once (stream-ordered before merge's atomics).
    if (bid == 0 && tid < 128) {
        #pragma unroll
        for (int j = 0; j < KCODES / 128; j++) g_hist[tid + j * 128] = 0;
    }

    // Stage tile transposed + tile norms. Threads <128 own one full code row
    // each: the norm stays the sequential in-order d=0..63 FMA chain
    // (reference rounding, bit-exact).
    if (tid < TK) {
        const float4* src = (const float4*)(emb + (size_t)(kt0 + tid) * DDIM);
        float nsum = 0.f;
        #pragma unroll
        for (int i = 0; i < DDIM / 4; i++) {
            float4 v = src[i];
            sEt[4 * i + 0][tid] = v.x;
            sEt[4 * i + 1][tid] = v.y;
            sEt[4 * i + 2][tid] = v.z;
            sEt[4 * i + 3][tid] = v.w;
            nsum = fmaf(v.x, v.x, nsum);
            nsum = fmaf(v.y, v.y, nsum);
            nsum = fmaf(v.z, v.z, nsum);
            nsum = fmaf(v.w, v.w, nsum);
        }
        sN[tid] = nsum;
    }

    // One point per thread.
    const int p = g * 256 + tid;
    const float* xp = z_e + (size_t)(p >> 10) * (DDIM * HWSZ) + (p & 1023);

    float x[DDIM];
    #pragma unroll
    for (int d = 0; d < DDIM; d++) x[d] = xp[(size_t)d * HWSZ];

    float nx = 0.f;
    #pragma unroll
    for (int d = 0; d < DDIM; d++) nx = fmaf(x[d], x[d], nx);

    // Exact -2 prescale: chain accumulates -fl(2*dot) with reference rounding.
    #pragma unroll
    for (int d = 0; d < DDIM; d++) x[d] = -2.f * x[d];

    __syncthreads();

    float best = __int_as_float(0x7f800000);
    int   bk   = kt0;

    #pragma unroll 1
    for (int kk = 0; kk < TK; kk += 8) {
        const ulonglong2* rp = (const ulonglong2*)&sEt[0][kk];
        unsigned long long a0 = 0, a1 = 0, a2 = 0, a3 = 0;
        // 4 packed chains = 8 codes; each lane is the sequential d=0..63
        // fmaf order: bit-identical to the reference dot product.
        #pragma unroll
        for (int d = 0; d < DDIM; d++) {
            ulonglong2 q0 = rp[d * (TK / 4)];
            ulonglong2 q1 = rp[d * (TK / 4) + 1];
            unsigned long long xx = splat2(x[d]);
            a0 = fma2(xx, q0.x, a0);
            a1 = fma2(xx, q0.y, a1);
            a2 = fma2(xx, q1.x, a2);
            a3 = fma2(xx, q1.y, a3);
        }
        float t0, t1, t2, t3, t4, t5, t6, t7, dd;
        unpack2(a0, t0, t1); unpack2(a1, t2, t3);
        unpack2(a2, t4, t5); unpack2(a3, t6, t7);
        // dist = fl( fl(nx+ne) + (-2dot) ); strict < ascending k == ref tie rule
        dd = (nx + sN[kk + 0]) + t0; if (dd < best) { best = dd; bk = kt0 + kk + 0; }
        dd = (nx + sN[kk + 1]) + t1; if (dd < best) { best = dd; bk = kt0 + kk + 1; }
        dd = (nx + sN[kk + 2]) + t2; if (dd < best) { best = dd; bk = kt0 + kk + 2; }
        dd = (nx + sN[kk + 3]) + t3; if (dd < best) { best = dd; bk = kt0 + kk + 3; }
        dd = (nx + sN[kk + 4]) + t4; if (dd < best) { best = dd; bk = kt0 + kk + 4; }
        dd = (nx + sN[kk + 5]) + t5; if (dd < best) { best = dd; bk = kt0 + kk + 5; }
        dd = (nx + sN[kk + 6]) + t6; if (dd < best) { best = dd; bk = kt0 + kk + 6; }
        dd = (nx + sN[kk + 7]) + t7; if (dd < best) { best = dd; bk = kt0 + kk + 7; }
    }

    g_pd[s * NPTS + p] = best;
    g_pk[s * NPTS + p] = bk;
}

// Kernel 2: merge partials (ascending split == ascending k: exact ref tie rule),
// then epilogue: z_st, one-hot, histogram atomics, loss partials.
__global__ void __launch_bounds__(128) vq_merge(const float* __restrict__ z_e,
                                                const float* __restrict__ emb,
                                                float* __restrict__ out) {
    __shared__ float sRed[4];
    const int tid = threadIdx.x;
    const int n   = blockIdx.x * 128 + tid;
    const int b   = n >> 10;
    const int hw  = n & 1023;

    float best = __int_as_float(0x7f800000);
    int   bk   = 0;
    #pragma unroll
    for (int s = 0; s < NSPLIT; s++) {
        float d = g_pd[s * NPTS + n];
        int   k = g_pk[s * NPTS + n];
        if (d < best) { best = d; bk = k; }
    }
    atomicAdd(&g_hist[bk], 1);

    // Epilogue: bit-exact reference op sequence z + (z_q - z)
    const float* xp = z_e + (size_t)b * (DDIM * HWSZ) + hw;
    const float* eq = emb + (size_t)bk * DDIM;
    float* zst = out + (size_t)b * (DDIM * HWSZ) + hw;
    float lsum = 0.f;
    #pragma unroll
    for (int d = 0; d < DDIM; d++) {
        float z  = xp[(size_t)d * HWSZ];
        float t  = eq[d] - z;
        __stcs(&zst[(size_t)d * HWSZ], z + t);
        lsum = fmaf(t, t, lsum);
    }
    __stcs(out + (size_t)OFF_ENC + (size_t)n * KCODES + bk, 1.0f);

    #pragma unroll
    for (int off = 16; off; off >>= 1)
        lsum += __shfl_down_sync(0xffffffffu, lsum, off);
    if ((tid & 31) == 0) sRed[tid >> 5] = lsum;
    __syncthreads();
    if (tid == 0)
        g_losspart[blockIdx.x] = (sRed[0] + sRed[1]) + (sRed[2] + sRed[3]);
}

// Kernel 3: entropy over histogram + loss partial sum
__global__ void __launch_bounds__(1024) vq_final(float* __restrict__ out) {
    __shared__ float red[KCODES];
    int t = threadIdx.x;

    float p = (float)g_hist[t] * (1.f / 32768.f);   // exact: /2^15
    red[t] = p * logf(p + 1e-10f);
    __syncthreads();
    #pragma unroll
    for (int s = 512; s; s >>= 1) {
        if (t < s) red[t] += red[t + s];
        __syncthreads();
    }
    float S = red[0];
    __syncthreads();

    red[t] = (t < 256) ? g_losspart[t] : 0.f;
    __syncthreads();
    #pragma unroll
    for (int s = 512; s; s >>= 1) {
        if (t < s) red[t] += red[t + s];
        __syncthreads();
    }
    if (t == 0) {
        float m = red[0] * (1.f / 2097152.f);       // exact: /2^21
        out[OFF_LOSS] = m + 0.25f * m;
        out[OFF_PERP] = expf(-S);
    }
}

extern "C" void kernel_launch(void* const* d_in, const int* in_sizes, int n_in,
                              void* d_out, int out_size) {
    const float* z_e = (const float*)d_in[0];
    const float* emb = (const float*)d_in[1];
    float* out = (float*)d_out;

    vq_main <<<NGRP * NSPLIT, 256>>>(z_e, emb, out);
    vq_merge<<<NPTS / 128, 128>>>(z_e, emb, out);
    vq_final<<<1, 1024>>>(out);
    (void)in_sizes; (void)n_in; (void)out_size;
}